// round 7
// baseline (speedup 1.0000x reference)
#include <cuda_runtime.h>
#include <cuda_fp16.h>
#include <cstdint>

// out[b,s,o] = sum_d x[b,s,d] * w[layer_idx[s], o, d]
// B=32, S=256, D=1024, O=1024, L=32, fp32.
//
// R7: conversions fused into the GEMM producer. No conv_w/conv_x kernels:
// the producer LDGs f32 x/w, converts to fp16 in regs, STS into the
// double-buffered tiles. 2-stage smem (72KB), one barrier per K-slab,
// plain fp16 mma.sync (rel_err ~2.9e-4 < 1e-3), 2 CTAs/SM.

constexpr int B_ = 32, S_ = 256, D_ = 1024, O_ = 1024, L_ = 32;
constexpr int KSLAB = 64, NSLABS = D_ / KSLAB;   // 16 slabs
constexpr int MAXT = 96;
constexpr int THREADS = 256;
constexpr int ROWB = 144;                         // 128B fp16 data + 16B pad
constexpr int SA = 0, SB = 18432;                 // 128 rows x 144B each
constexpr int STAGE = 36864;
constexpr int SMEM_TOTAL = 2 * STAGE;             // 73728 B

// ---- device scratch ----
__device__ int g_tile_pos[MAXT * 4];
__device__ int g_tile_layer[MAXT];
__device__ int g_ntiles;

// ---------------- helpers ----------------
__device__ __forceinline__ uint32_t smem_u32(const void* p) {
    uint32_t a;
    asm("{ .reg .u64 t; cvta.to.shared.u64 t, %1; cvt.u32.u64 %0, t; }" : "=r"(a) : "l"(p));
    return a;
}
__device__ __forceinline__ void ldsm4(uint32_t* r, uint32_t addr) {
    asm volatile("ldmatrix.sync.aligned.m8n8.x4.shared.b16 {%0,%1,%2,%3}, [%4];"
                 : "=r"(r[0]), "=r"(r[1]), "=r"(r[2]), "=r"(r[3]) : "r"(addr));
}
__device__ __forceinline__ void mma16816(float* c, const uint32_t* a, const uint32_t* b) {
    asm volatile(
        "mma.sync.aligned.m16n8k16.row.col.f32.f16.f16.f32 "
        "{%0,%1,%2,%3}, {%4,%5,%6,%7}, {%8,%9}, {%0,%1,%2,%3};"
        : "+f"(c[0]), "+f"(c[1]), "+f"(c[2]), "+f"(c[3])
        : "r"(a[0]), "r"(a[1]), "r"(a[2]), "r"(a[3]), "r"(b[0]), "r"(b[1]));
}
__device__ __forceinline__ uint32_t pk2(float a, float b) {
    __half2 h = __floats2half2_rn(a, b);
    return *reinterpret_cast<uint32_t*>(&h);
}

// ---------------- planning: sort positions by layer into 4-pos tiles ------
__global__ void plan_kernel(const int* __restrict__ layer_idx) {
    __shared__ int sidx[S_];
    __shared__ int tbase[L_ + 1];
    int t = threadIdx.x;  // 256 threads
    sidx[t] = layer_idx[t];
    g_tile_pos[t] = -1;
    if (t < MAXT * 4 - S_) g_tile_pos[S_ + t] = -1;
    __syncthreads();

    int my_l = sidx[t];
    int rank = 0;
    for (int j = 0; j < t; j++) rank += (sidx[j] == my_l) ? 1 : 0;

    if (t == 0) {
        int cnt[L_];
        for (int l = 0; l < L_; l++) cnt[l] = 0;
        for (int j = 0; j < S_; j++) cnt[sidx[j]]++;
        int acc = 0;
        for (int l = 0; l < L_; l++) { tbase[l] = acc; acc += (cnt[l] + 3) >> 2; }
        g_ntiles = acc;
    }
    __syncthreads();

    int tile = tbase[my_l] + (rank >> 2);
    g_tile_pos[tile * 4 + (rank & 3)] = t;
    if ((rank & 3) == 0) g_tile_layer[tile] = my_l;
}

// ---------------- grouped GEMM: fp16 mma.sync, fused f32->fp16 ----------
extern __shared__ char smem[];

__global__ __launch_bounds__(THREADS, 2)
void moshi_gemm_kernel(const float* __restrict__ x,
                       const float* __restrict__ w,
                       float* __restrict__ out) {
    const int tile = blockIdx.y;
    if (tile >= g_ntiles) return;

    const int tid = threadIdx.x;
    const int lane = tid & 31;
    const int wid = tid >> 5;
    const int warp_m = wid & 1;        // 2 warps in M
    const int warp_n = wid >> 1;       // 4 warps in N
    const int m64 = warp_m * 64;
    const int n32 = warp_n * 32;
    const int otile = blockIdx.x * 128;
    const int l = g_tile_layer[tile];
    const uint32_t sbase = smem_u32(smem);

    // ---- producer mapping: row = tid>>1 (0..127); half = tid&1 (32 f32) ----
    const int ar = tid >> 1;
    const int half = tid & 1;
    const int aslot = ar >> 5;
    const int aspos = g_tile_pos[tile * 4 + aslot];
    const bool avalid = (aspos >= 0);
    const float* ax = avalid
        ? (x + ((size_t)(ar & 31) * S_ + aspos) * D_ + half * 32) : x;
    const float* bw = w + ((size_t)l * O_ + otile + ar) * D_ + half * 32;
    const uint32_t dRow = (uint32_t)ar * ROWB + half * 64;

    // ---- ldmatrix lane offsets ----
    const uint32_t aOff = (uint32_t)(m64 + (lane & 15)) * ROWB + (lane >> 4) * 16;
    const uint32_t bOff = (uint32_t)(n32 + (lane & 7) + ((lane >> 4) << 3)) * ROWB
                          + ((lane >> 3) & 1) * 16;

    float acc[4][4][4];
#pragma unroll
    for (int i = 0; i < 4; i++)
#pragma unroll
        for (int j = 0; j < 4; j++)
#pragma unroll
            for (int q = 0; q < 4; q++) acc[i][j][q] = 0.0f;

    // producer: LDG 8 float4 per matrix, cvt, 4 STS.128 per matrix
    auto produce = [&](int slab) {
        const uint32_t s0 = sbase + (slab & 1) * STAGE;
        const int k0 = slab * KSLAB;
        float4 va[8];
        if (avalid) {
#pragma unroll
            for (int i = 0; i < 8; i++) va[i] = *(const float4*)(ax + k0 + 4 * i);
        } else {
#pragma unroll
            for (int i = 0; i < 8; i++) va[i] = make_float4(0.f, 0.f, 0.f, 0.f);
        }
        float4 vb[8];
#pragma unroll
        for (int i = 0; i < 8; i++) vb[i] = *(const float4*)(bw + k0 + 4 * i);
#pragma unroll
        for (int c = 0; c < 4; c++) {
            uint4 pa = make_uint4(pk2(va[2 * c].x, va[2 * c].y),
                                  pk2(va[2 * c].z, va[2 * c].w),
                                  pk2(va[2 * c + 1].x, va[2 * c + 1].y),
                                  pk2(va[2 * c + 1].z, va[2 * c + 1].w));
            *(uint4*)(smem + ((s0 - sbase) + SA + dRow + c * 16)) = pa;
            uint4 pb = make_uint4(pk2(vb[2 * c].x, vb[2 * c].y),
                                  pk2(vb[2 * c].z, vb[2 * c].w),
                                  pk2(vb[2 * c + 1].x, vb[2 * c + 1].y),
                                  pk2(vb[2 * c + 1].z, vb[2 * c + 1].w));
            *(uint4*)(smem + ((s0 - sbase) + SB + dRow + c * 16)) = pb;
        }
    };

    produce(0);
    __syncthreads();

    for (int s = 0; s < NSLABS; s++) {
        const uint32_t sstage = sbase + (s & 1) * STAGE;
#pragma unroll
        for (int kk = 0; kk < 4; kk++) {
            uint32_t ah[4][4];
#pragma unroll
            for (int mi = 0; mi < 4; mi++)
                ldsm4(ah[mi], sstage + SA + aOff + mi * (16 * ROWB) + kk * 32);
            uint32_t bb[4][2];
#pragma unroll
            for (int p = 0; p < 2; p++) {
                uint32_t r[4];
                ldsm4(r, sstage + SB + bOff + p * (16 * ROWB) + kk * 32);
                bb[2 * p][0] = r[0]; bb[2 * p][1] = r[1];
                bb[2 * p + 1][0] = r[2]; bb[2 * p + 1][1] = r[3];
            }
#pragma unroll
            for (int mi = 0; mi < 4; mi++)
#pragma unroll
                for (int ni = 0; ni < 4; ni++)
                    mma16816(acc[mi][ni], ah[mi], bb[ni]);
        }
        if (s + 1 < NSLABS) produce(s + 1);
        __syncthreads();
    }

    // ---- epilogue: c frag -> out[b, spos, o] ----
    const int gcol = otile + n32 + 2 * (lane & 3);
#pragma unroll
    for (int mi = 0; mi < 4; mi++) {
        const int row0 = m64 + mi * 16 + (lane >> 2);
        const int slot = row0 >> 5;
        const int spos = g_tile_pos[tile * 4 + slot];
        if (spos < 0) continue;
        float* base0 = out + ((size_t)(row0 & 31) * S_ + spos) * O_ + gcol;
        float* base1 = out + ((size_t)((row0 + 8) & 31) * S_ + spos) * O_ + gcol;
#pragma unroll
        for (int ni = 0; ni < 4; ni++) {
            *(float2*)(base0 + ni * 8) = make_float2(acc[mi][ni][0], acc[mi][ni][1]);
            *(float2*)(base1 + ni * 8) = make_float2(acc[mi][ni][2], acc[mi][ni][3]);
        }
    }
}

extern "C" void kernel_launch(void* const* d_in, const int* in_sizes, int n_in,
                              void* d_out, int out_size) {
    const float* x = (const float*)d_in[0];
    const int* idx = (const int*)d_in[1];
    const float* w = (const float*)d_in[2];
    float* out = (float*)d_out;

    plan_kernel<<<1, S_>>>(idx);

    static bool attr_set = false;
    if (!attr_set) {
        cudaFuncSetAttribute(moshi_gemm_kernel,
                             cudaFuncAttributeMaxDynamicSharedMemorySize, SMEM_TOTAL);
        attr_set = true;
    }
    dim3 grid(O_ / 128, MAXT);  // (8, 96); blocks beyond g_ntiles exit
    moshi_gemm_kernel<<<grid, THREADS, SMEM_TOTAL>>>(x, w, out);
}

// round 9
// speedup vs baseline: 1.5148x; 1.5148x over previous
#include <cuda_runtime.h>
#include <cuda_fp16.h>
#include <cstdint>

// out[b,s,o] = sum_d x[b,s,d] * w[layer_idx[s], o, d]
// B=32, S=256, D=1024, O=1024, L=32, fp32.
//
// R9: R8 (3-stage mbarrier producer/consumer pipeline, no __syncthreads in
// the mainloop) with the deadlock fixed: cp.async.mbarrier.arrive must be the
// .noinc form when the barrier is initialized with count = THREADS (the
// default form increments pending count first -> barrier never completes).

constexpr int B_ = 32, S_ = 256, D_ = 1024, O_ = 1024, L_ = 32;
constexpr int KSLAB = 64, NSLABS = D_ / KSLAB;   // 16 slabs
constexpr int MAXT = 96;
constexpr int THREADS = 256;
constexpr int ROWB = 144;                         // 128B data + 16B pad
constexpr int SA = 0, SB = 18432;                 // within a stage
constexpr int STAGE = 36864;
constexpr int NSTAGE = 3;
constexpr int SM_MBAR = 0;                        // full[st]=st*16, empty[st]=+8
constexpr int SM_TILES = 128;
constexpr int SMEM_TOTAL = SM_TILES + NSTAGE * STAGE;  // 110720 B

// ---- device scratch (no allocs allowed) ----
__device__ __half g_w16[(size_t)L_ * O_ * D_];
__device__ __half g_x16[(size_t)S_ * B_ * D_];    // [s][b][d]
__device__ int g_tile_pos[MAXT * 4];
__device__ int g_tile_layer[MAXT];
__device__ int g_ntiles;

// ---------------- helpers ----------------
__device__ __forceinline__ uint32_t smem_u32(const void* p) {
    uint32_t a;
    asm("{ .reg .u64 t; cvta.to.shared.u64 t, %1; cvt.u32.u64 %0, t; }" : "=r"(a) : "l"(p));
    return a;
}
__device__ __forceinline__ void cp16(uint32_t dst, const void* src, int srcsz) {
    asm volatile("cp.async.cg.shared.global [%0], [%1], 16, %2;"
                 :: "r"(dst), "l"(src), "r"(srcsz));
}
#define MBAR_INIT(addr, cnt) \
    asm volatile("mbarrier.init.shared.b64 [%0], %1;" :: "r"(addr), "r"(cnt) : "memory")
#define MBAR_ARRIVE(addr) \
    asm volatile("mbarrier.arrive.shared.b64 _, [%0];" :: "r"(addr) : "memory")
// .noinc: arrive without bumping pending count (barrier pre-armed with THREADS)
#define CP_MBAR_ARRIVE(addr) \
    asm volatile("cp.async.mbarrier.arrive.noinc.shared.b64 [%0];" :: "r"(addr) : "memory")
#define MBAR_WAIT(addr, par) do {                                              \
    uint32_t _m = (addr), _p = (par), _d;                                      \
    asm volatile("{ .reg .pred p; mbarrier.try_wait.parity.acquire.cta.shared::cta.b64 p, [%1], %2; selp.b32 %0,1,0,p; }" \
        : "=r"(_d) : "r"(_m), "r"(_p) : "memory");                             \
    if (!_d) {                                                                 \
        asm volatile("{ .reg .pred P; WL_%=: mbarrier.try_wait.parity.acquire.cta.shared::cta.b64 P, [%0], %1, 0x989680; @P bra.uni WD_%=; bra.uni WL_%=; WD_%=: }" \
            :: "r"(_m), "r"(_p) : "memory");                                   \
    }                                                                          \
} while (0)

__device__ __forceinline__ void ldsm4(uint32_t* r, uint32_t addr) {
    asm volatile("ldmatrix.sync.aligned.m8n8.x4.shared.b16 {%0,%1,%2,%3}, [%4];"
                 : "=r"(r[0]), "=r"(r[1]), "=r"(r[2]), "=r"(r[3]) : "r"(addr));
}
__device__ __forceinline__ void mma16816(float* c, const uint32_t* a, const uint32_t* b) {
    asm volatile(
        "mma.sync.aligned.m16n8k16.row.col.f32.f16.f16.f32 "
        "{%0,%1,%2,%3}, {%4,%5,%6,%7}, {%8,%9}, {%0,%1,%2,%3};"
        : "+f"(c[0]), "+f"(c[1]), "+f"(c[2]), "+f"(c[3])
        : "r"(a[0]), "r"(a[1]), "r"(a[2]), "r"(a[3]), "r"(b[0]), "r"(b[1]));
}

// ---------------- precompute: fp32 -> fp16 for W and X(transposed) --------
constexpr int WBLKS = (L_ * O_ * D_) / 4 / 256;   // 32768
constexpr int XBLKS = (S_ * B_ * D_) / 4 / 256;   // 8192

__global__ void conv_kernel(const float* __restrict__ w, const float* __restrict__ x) {
    uint32_t bid = blockIdx.x;
    if (bid < WBLKS) {
        size_t i4 = ((size_t)bid * 256 + threadIdx.x) * 4;
        float4 v = *(const float4*)(w + i4);
        __half2 h0 = __floats2half2_rn(v.x, v.y);
        __half2 h1 = __floats2half2_rn(v.z, v.w);
        uint2 pk;
        pk.x = *reinterpret_cast<uint32_t*>(&h0);
        pk.y = *reinterpret_cast<uint32_t*>(&h1);
        *(uint2*)(g_w16 + i4) = pk;
    } else {
        uint32_t e4 = (bid - WBLKS) * 256 + threadIdx.x;
        int d4 = e4 & 255;
        int b  = (e4 >> 8) & 31;
        int s  = e4 >> 13;
        float4 v = *(const float4*)(x + ((size_t)b * S_ + s) * D_ + d4 * 4);
        size_t o4 = (size_t)e4 * 4;
        __half2 h0 = __floats2half2_rn(v.x, v.y);
        __half2 h1 = __floats2half2_rn(v.z, v.w);
        uint2 ph;
        ph.x = *reinterpret_cast<uint32_t*>(&h0);
        ph.y = *reinterpret_cast<uint32_t*>(&h1);
        *(uint2*)(g_x16 + o4) = ph;
    }
}

// ---------------- planning: sort positions by layer into 4-pos tiles ------
__global__ void plan_kernel(const int* __restrict__ layer_idx) {
    __shared__ int sidx[S_];
    __shared__ int tbase[L_ + 1];
    int t = threadIdx.x;  // 256 threads
    sidx[t] = layer_idx[t];
    g_tile_pos[t] = -1;
    if (t < MAXT * 4 - S_) g_tile_pos[S_ + t] = -1;
    __syncthreads();

    int my_l = sidx[t];
    int rank = 0;
    for (int j = 0; j < t; j++) rank += (sidx[j] == my_l) ? 1 : 0;

    if (t == 0) {
        int cnt[L_];
        for (int l = 0; l < L_; l++) cnt[l] = 0;
        for (int j = 0; j < S_; j++) cnt[sidx[j]]++;
        int acc = 0;
        for (int l = 0; l < L_; l++) { tbase[l] = acc; acc += (cnt[l] + 3) >> 2; }
        g_ntiles = acc;
    }
    __syncthreads();

    int tile = tbase[my_l] + (rank >> 2);
    g_tile_pos[tile * 4 + (rank & 3)] = t;
    if ((rank & 3) == 0) g_tile_layer[tile] = my_l;
}

// ---------------- grouped GEMM: fp16 mma.sync, mbarrier pipeline ----------
extern __shared__ char smem[];

__global__ __launch_bounds__(THREADS, 2)
void moshi_gemm_kernel(float* __restrict__ out) {
    const int tile = blockIdx.y;
    if (tile >= g_ntiles) return;

    const int tid = threadIdx.x;
    const int lane = tid & 31;
    const int wid = tid >> 5;
    const int warp_m = wid & 1;        // 2 warps in M
    const int warp_n = wid >> 1;       // 4 warps in N
    const int m64 = warp_m * 64;
    const int n32 = warp_n * 32;
    const int otile = blockIdx.x * 128;
    const int l = g_tile_layer[tile];
    const uint32_t sbase = smem_u32(smem);

    // mbarriers: full[st] = SM_MBAR + st*16 (armed for 256 cp-arrives),
    //            empty[st] = +8 (armed for 256 consumer arrives)
    if (tid == 0) {
#pragma unroll
        for (int st = 0; st < NSTAGE; st++) {
            MBAR_INIT(sbase + SM_MBAR + st * 16, THREADS);
            MBAR_INIT(sbase + SM_MBAR + st * 16 + 8, THREADS);
        }
    }
    __syncthreads();

    // ---- producer mapping: row = tid>>1, 4 chunks at (tid&1)*4 ----
    const int ar = tid >> 1;
    const int acp = (tid & 1) * 4;
    const int aslot = ar >> 5;
    const int aspos = g_tile_pos[tile * 4 + aslot];
    int asz = 16;
    size_t axoff = 0;
    if (aspos >= 0) axoff = ((size_t)aspos * B_ + (ar & 31)) * D_ + acp * 8;
    else asz = 0;
    const __half* ax = g_x16 + axoff;
    const __half* bw = g_w16 + ((size_t)l * O_ + otile + ar) * D_ + acp * 8;
    const uint32_t dRow = (uint32_t)ar * ROWB + acp * 16;

    // ---- ldmatrix lane offsets ----
    const uint32_t aOff = (uint32_t)(m64 + (lane & 15)) * ROWB + (lane >> 4) * 16;
    const uint32_t bOff = (uint32_t)(n32 + (lane & 7) + ((lane >> 4) << 3)) * ROWB
                          + ((lane >> 3) & 1) * 16;

    float acc[4][4][4];
#pragma unroll
    for (int i = 0; i < 4; i++)
#pragma unroll
        for (int j = 0; j < 4; j++)
#pragma unroll
            for (int q = 0; q < 4; q++) acc[i][j][q] = 0.0f;

    auto produce = [&](int slab) {
        const int st = slab % NSTAGE;
        const uint32_t s0 = sbase + SM_TILES + st * STAGE;
        const int k0 = slab * KSLAB;
#pragma unroll
        for (int c = 0; c < 4; c++) {
            cp16(s0 + SA + dRow + c * 16, ax + k0 + c * 8, asz);
            cp16(s0 + SB + dRow + c * 16, bw + k0 + c * 8, 16);
        }
        CP_MBAR_ARRIVE(sbase + SM_MBAR + st * 16);
    };

    produce(0);
    produce(1);

    for (int s = 0; s < NSLABS; s++) {
        const int st = s % NSTAGE;
        // produce slab s+2 into stage (s+2)%3 (released by consumers of s-1)
        const int ps = s + 2;
        if (ps < NSLABS) {
            const int pw = ps / NSTAGE;
            if (pw >= 1) MBAR_WAIT(sbase + SM_MBAR + (ps % NSTAGE) * 16 + 8, (pw - 1) & 1);
            produce(ps);
        }
        // consume slab s (fill # s/3)
        MBAR_WAIT(sbase + SM_MBAR + st * 16, (s / NSTAGE) & 1);
        const uint32_t sstage = sbase + SM_TILES + st * STAGE;
#pragma unroll
        for (int kk = 0; kk < 4; kk++) {
            uint32_t ah[4][4];
#pragma unroll
            for (int mi = 0; mi < 4; mi++)
                ldsm4(ah[mi], sstage + SA + aOff + mi * (16 * ROWB) + kk * 32);
            uint32_t bb[4][2];
#pragma unroll
            for (int p = 0; p < 2; p++) {
                uint32_t r[4];
                ldsm4(r, sstage + SB + bOff + p * (16 * ROWB) + kk * 32);
                bb[2 * p][0] = r[0]; bb[2 * p][1] = r[1];
                bb[2 * p + 1][0] = r[2]; bb[2 * p + 1][1] = r[3];
            }
#pragma unroll
            for (int mi = 0; mi < 4; mi++)
#pragma unroll
                for (int ni = 0; ni < 4; ni++)
                    mma16816(acc[mi][ni], ah[mi], bb[ni]);
        }
        MBAR_ARRIVE(sbase + SM_MBAR + st * 16 + 8);
    }

    // ---- epilogue: c frag -> out[b, spos, o] ----
    const int gcol = otile + n32 + 2 * (lane & 3);
#pragma unroll
    for (int mi = 0; mi < 4; mi++) {
        const int row0 = m64 + mi * 16 + (lane >> 2);
        const int slot = row0 >> 5;
        const int spos = g_tile_pos[tile * 4 + slot];
        if (spos < 0) continue;
        float* base0 = out + ((size_t)(row0 & 31) * S_ + spos) * O_ + gcol;
        float* base1 = out + ((size_t)((row0 + 8) & 31) * S_ + spos) * O_ + gcol;
#pragma unroll
        for (int ni = 0; ni < 4; ni++) {
            *(float2*)(base0 + ni * 8) = make_float2(acc[mi][ni][0], acc[mi][ni][1]);
            *(float2*)(base1 + ni * 8) = make_float2(acc[mi][ni][2], acc[mi][ni][3]);
        }
    }
}

extern "C" void kernel_launch(void* const* d_in, const int* in_sizes, int n_in,
                              void* d_out, int out_size) {
    const float* x = (const float*)d_in[0];
    const int* idx = (const int*)d_in[1];
    const float* w = (const float*)d_in[2];
    float* out = (float*)d_out;

    conv_kernel<<<WBLKS + XBLKS, 256>>>(w, x);
    plan_kernel<<<1, S_>>>(idx);

    static bool attr_set = false;
    if (!attr_set) {
        cudaFuncSetAttribute(moshi_gemm_kernel,
                             cudaFuncAttributeMaxDynamicSharedMemorySize, SMEM_TOTAL);
        attr_set = true;
    }
    dim3 grid(O_ / 128, MAXT);  // (8, 96); blocks beyond g_ntiles exit
    moshi_gemm_kernel<<<grid, THREADS, SMEM_TOTAL>>>(out);
}

// round 10
// speedup vs baseline: 1.5361x; 1.0140x over previous
#include <cuda_runtime.h>
#include <cuda_fp16.h>
#include <cstdint>

// out[b,s,o] = sum_d x[b,s,d] * w[layer_idx[s], o, d]
// B=32, S=256, D=1024, O=1024, L=32, fp32.
//
// R10: persistent grouped GEMM. 304 CTAs (2/SM), each loops over work items
// (tile, nb) as ONE continuous K-slab stream through the 3-stage mbarrier
// pipeline -- no drain/re-init between items, epilogue overlaps the next
// item's loads. conv+plan merged into one launch.

constexpr int B_ = 32, S_ = 256, D_ = 1024, O_ = 1024, L_ = 32;
constexpr int KSLAB = 64, NSLABS = D_ / KSLAB;   // 16 slabs per item
constexpr int MAXT = 96;
constexpr int THREADS = 256;
constexpr int NPERS = 304;                        // 2 x 152 SMs
constexpr int ROWB = 144;                         // 128B data + 16B pad
constexpr int SA = 0, SB = 18432;                 // within a stage
constexpr int STAGE = 36864;
constexpr int NSTAGE = 3;
constexpr int SM_MBAR = 0;                        // full[st]=st*16, empty[st]=+8
constexpr int SM_TILES = 128;
constexpr int SMEM_TOTAL = SM_TILES + NSTAGE * STAGE;  // 110720 B

// ---- device scratch (no allocs allowed) ----
__device__ __half g_w16[(size_t)L_ * O_ * D_];
__device__ __half g_x16[(size_t)S_ * B_ * D_];    // [s][b][d]
__device__ int g_tile_pos[MAXT * 4];
__device__ int g_tile_layer[MAXT];
__device__ int g_ntiles;

// ---------------- helpers ----------------
__device__ __forceinline__ uint32_t smem_u32(const void* p) {
    uint32_t a;
    asm("{ .reg .u64 t; cvta.to.shared.u64 t, %1; cvt.u32.u64 %0, t; }" : "=r"(a) : "l"(p));
    return a;
}
__device__ __forceinline__ void cp16(uint32_t dst, const void* src, int srcsz) {
    asm volatile("cp.async.cg.shared.global [%0], [%1], 16, %2;"
                 :: "r"(dst), "l"(src), "r"(srcsz));
}
#define MBAR_INIT(addr, cnt) \
    asm volatile("mbarrier.init.shared.b64 [%0], %1;" :: "r"(addr), "r"(cnt) : "memory")
#define MBAR_ARRIVE(addr) \
    asm volatile("mbarrier.arrive.shared.b64 _, [%0];" :: "r"(addr) : "memory")
#define CP_MBAR_ARRIVE(addr) \
    asm volatile("cp.async.mbarrier.arrive.noinc.shared.b64 [%0];" :: "r"(addr) : "memory")
#define MBAR_WAIT(addr, par) do {                                              \
    uint32_t _m = (addr), _p = (par), _d;                                      \
    asm volatile("{ .reg .pred p; mbarrier.try_wait.parity.acquire.cta.shared::cta.b64 p, [%1], %2; selp.b32 %0,1,0,p; }" \
        : "=r"(_d) : "r"(_m), "r"(_p) : "memory");                             \
    if (!_d) {                                                                 \
        asm volatile("{ .reg .pred P; WL_%=: mbarrier.try_wait.parity.acquire.cta.shared::cta.b64 P, [%0], %1, 0x989680; @P bra.uni WD_%=; bra.uni WL_%=; WD_%=: }" \
            :: "r"(_m), "r"(_p) : "memory");                                   \
    }                                                                          \
} while (0)

__device__ __forceinline__ void ldsm4(uint32_t* r, uint32_t addr) {
    asm volatile("ldmatrix.sync.aligned.m8n8.x4.shared.b16 {%0,%1,%2,%3}, [%4];"
                 : "=r"(r[0]), "=r"(r[1]), "=r"(r[2]), "=r"(r[3]) : "r"(addr));
}
__device__ __forceinline__ void mma16816(float* c, const uint32_t* a, const uint32_t* b) {
    asm volatile(
        "mma.sync.aligned.m16n8k16.row.col.f32.f16.f16.f32 "
        "{%0,%1,%2,%3}, {%4,%5,%6,%7}, {%8,%9}, {%0,%1,%2,%3};"
        : "+f"(c[0]), "+f"(c[1]), "+f"(c[2]), "+f"(c[3])
        : "r"(a[0]), "r"(a[1]), "r"(a[2]), "r"(a[3]), "r"(b[0]), "r"(b[1]));
}

// ---------------- precompute + plan, one launch ----------------
constexpr int WBLKS = (L_ * O_ * D_) / 4 / 256;   // 32768
constexpr int XBLKS = (S_ * B_ * D_) / 4 / 256;   // 8192

__global__ void conv_kernel(const float* __restrict__ w, const float* __restrict__ x,
                            const int* __restrict__ layer_idx) {
    __shared__ int sidx[S_];
    __shared__ int tbase[L_ + 1];
    uint32_t bid = blockIdx.x;
    if (bid < WBLKS) {
        size_t i4 = ((size_t)bid * 256 + threadIdx.x) * 4;
        float4 v = *(const float4*)(w + i4);
        __half2 h0 = __floats2half2_rn(v.x, v.y);
        __half2 h1 = __floats2half2_rn(v.z, v.w);
        uint2 pk;
        pk.x = *reinterpret_cast<uint32_t*>(&h0);
        pk.y = *reinterpret_cast<uint32_t*>(&h1);
        *(uint2*)(g_w16 + i4) = pk;
    } else if (bid < WBLKS + XBLKS) {
        uint32_t e4 = (bid - WBLKS) * 256 + threadIdx.x;
        int d4 = e4 & 255;
        int b  = (e4 >> 8) & 31;
        int s  = e4 >> 13;
        float4 v = *(const float4*)(x + ((size_t)b * S_ + s) * D_ + d4 * 4);
        size_t o4 = (size_t)e4 * 4;
        __half2 h0 = __floats2half2_rn(v.x, v.y);
        __half2 h1 = __floats2half2_rn(v.z, v.w);
        uint2 ph;
        ph.x = *reinterpret_cast<uint32_t*>(&h0);
        ph.y = *reinterpret_cast<uint32_t*>(&h1);
        *(uint2*)(g_x16 + o4) = ph;
    } else {
        // planning block: sort positions by layer into 4-pos tiles
        int t = threadIdx.x;
        sidx[t] = layer_idx[t];
        g_tile_pos[t] = -1;
        if (t < MAXT * 4 - S_) g_tile_pos[S_ + t] = -1;
        __syncthreads();
        int my_l = sidx[t];
        int rank = 0;
        for (int j = 0; j < t; j++) rank += (sidx[j] == my_l) ? 1 : 0;
        if (t == 0) {
            int cnt[L_];
            for (int l = 0; l < L_; l++) cnt[l] = 0;
            for (int j = 0; j < S_; j++) cnt[sidx[j]]++;
            int acc = 0;
            for (int l = 0; l < L_; l++) { tbase[l] = acc; acc += (cnt[l] + 3) >> 2; }
            g_ntiles = acc;
        }
        __syncthreads();
        int tile = tbase[my_l] + (rank >> 2);
        g_tile_pos[tile * 4 + (rank & 3)] = t;
        if ((rank & 3) == 0) g_tile_layer[tile] = my_l;
    }
}

// ---------------- persistent grouped GEMM ----------------
extern __shared__ char smem[];

__global__ __launch_bounds__(THREADS, 2)
void moshi_gemm_kernel(float* __restrict__ out) {
    const int tid = threadIdx.x;
    const int lane = tid & 31;
    const int wid = tid >> 5;
    const int warp_m = wid & 1;
    const int warp_n = wid >> 1;
    const int m64 = warp_m * 64;
    const int n32 = warp_n * 32;
    const uint32_t sbase = smem_u32(smem);

    const int n_items = g_ntiles * 8;          // (tile, nb) pairs
    // my items: blockIdx.x + li*NPERS, li = 0..my_n-1
    int my_n = 0;
    for (int it = blockIdx.x; it < n_items; it += NPERS) my_n++;
    if (my_n == 0) return;
    const int total_slabs = my_n * NSLABS;

    if (tid == 0) {
#pragma unroll
        for (int st = 0; st < NSTAGE; st++) {
            MBAR_INIT(sbase + SM_MBAR + st * 16, THREADS);
            MBAR_INIT(sbase + SM_MBAR + st * 16 + 8, THREADS);
        }
    }
    __syncthreads();

    // ---- fixed per-thread mappings ----
    const int ar = tid >> 1;            // producer row 0..127
    const int acp = (tid & 1) * 4;      // 4 x 16B chunks
    const int aslot = ar >> 5;
    const uint32_t dRow = (uint32_t)ar * ROWB + acp * 16;
    const uint32_t aOff = (uint32_t)(m64 + (lane & 15)) * ROWB + (lane >> 4) * 16;
    const uint32_t bOff = (uint32_t)(n32 + (lane & 7) + ((lane >> 4) << 3)) * ROWB
                          + ((lane >> 3) & 1) * 16;

    // ---- producer item state ----
    int p_li = -1;
    const __half* ax = g_x16;
    const __half* bw = g_w16;
    int asz = 0;

    auto setp = [&](int li) {
        const int item = blockIdx.x + li * NPERS;
        const int tile = item >> 3;
        const int nb = item & 7;
        const int l = g_tile_layer[tile];
        const int aspos = g_tile_pos[tile * 4 + aslot];
        asz = (aspos >= 0) ? 16 : 0;
        ax = g_x16 + ((aspos >= 0)
                ? ((size_t)aspos * B_ + (ar & 31)) * D_ + acp * 8 : 0);
        bw = g_w16 + ((size_t)l * O_ + nb * 128 + ar) * D_ + acp * 8;
    };

    auto produce = [&](int sg) {
        const int li = sg >> 4;                // item index
        if (li != p_li) { setp(li); p_li = li; }
        const int st = sg % NSTAGE;
        const uint32_t s0 = sbase + SM_TILES + st * STAGE;
        const int k0 = (sg & 15) * KSLAB;
#pragma unroll
        for (int c = 0; c < 4; c++) {
            cp16(s0 + SA + dRow + c * 16, ax + k0 + c * 8, asz);
            cp16(s0 + SB + dRow + c * 16, bw + k0 + c * 8, 16);
        }
        CP_MBAR_ARRIVE(sbase + SM_MBAR + st * 16);
    };

    float acc[4][4][4];
#pragma unroll
    for (int i = 0; i < 4; i++)
#pragma unroll
        for (int j = 0; j < 4; j++)
#pragma unroll
            for (int q = 0; q < 4; q++) acc[i][j][q] = 0.0f;

    produce(0);
    produce(1);

    for (int sg = 0; sg < total_slabs; sg++) {
        const int ps = sg + 2;
        if (ps < total_slabs) {
            const int pw = ps / NSTAGE;
            if (pw >= 1) MBAR_WAIT(sbase + SM_MBAR + (ps % NSTAGE) * 16 + 8, (pw - 1) & 1);
            produce(ps);
        }
        const int st = sg % NSTAGE;
        MBAR_WAIT(sbase + SM_MBAR + st * 16, (sg / NSTAGE) & 1);
        const uint32_t sstage = sbase + SM_TILES + st * STAGE;
#pragma unroll
        for (int kk = 0; kk < 4; kk++) {
            uint32_t ah[4][4];
#pragma unroll
            for (int mi = 0; mi < 4; mi++)
                ldsm4(ah[mi], sstage + SA + aOff + mi * (16 * ROWB) + kk * 32);
            uint32_t bb[4][2];
#pragma unroll
            for (int p = 0; p < 2; p++) {
                uint32_t r[4];
                ldsm4(r, sstage + SB + bOff + p * (16 * ROWB) + kk * 32);
                bb[2 * p][0] = r[0]; bb[2 * p][1] = r[1];
                bb[2 * p + 1][0] = r[2]; bb[2 * p + 1][1] = r[3];
            }
#pragma unroll
            for (int mi = 0; mi < 4; mi++)
#pragma unroll
                for (int ni = 0; ni < 4; ni++)
                    mma16816(acc[mi][ni], ah[mi], bb[ni]);
        }
        MBAR_ARRIVE(sbase + SM_MBAR + st * 16 + 8);

        // ---- item boundary: epilogue + acc reset ----
        if ((sg & 15) == 15) {
            const int item = blockIdx.x + (sg >> 4) * NPERS;
            const int tile = item >> 3;
            const int otile = (item & 7) * 128;
            const int gcol = otile + n32 + 2 * (lane & 3);
#pragma unroll
            for (int mi = 0; mi < 4; mi++) {
                const int row0 = m64 + mi * 16 + (lane >> 2);
                const int slot = row0 >> 5;
                const int spos = g_tile_pos[tile * 4 + slot];
                if (spos >= 0) {
                    float* base0 = out + ((size_t)(row0 & 31) * S_ + spos) * O_ + gcol;
                    float* base1 = out + ((size_t)((row0 + 8) & 31) * S_ + spos) * O_ + gcol;
#pragma unroll
                    for (int ni = 0; ni < 4; ni++) {
                        *(float2*)(base0 + ni * 8) =
                            make_float2(acc[mi][ni][0], acc[mi][ni][1]);
                        *(float2*)(base1 + ni * 8) =
                            make_float2(acc[mi][ni][2], acc[mi][ni][3]);
                    }
                }
#pragma unroll
                for (int ni = 0; ni < 4; ni++)
#pragma unroll
                    for (int q = 0; q < 4; q++) acc[mi][ni][q] = 0.0f;
            }
        }
    }
}

extern "C" void kernel_launch(void* const* d_in, const int* in_sizes, int n_in,
                              void* d_out, int out_size) {
    const float* x = (const float*)d_in[0];
    const int* idx = (const int*)d_in[1];
    const float* w = (const float*)d_in[2];
    float* out = (float*)d_out;

    conv_kernel<<<WBLKS + XBLKS + 1, 256>>>(w, x, idx);

    static bool attr_set = false;
    if (!attr_set) {
        cudaFuncSetAttribute(moshi_gemm_kernel,
                             cudaFuncAttributeMaxDynamicSharedMemorySize, SMEM_TOTAL);
        attr_set = true;
    }
    moshi_gemm_kernel<<<NPERS, THREADS, SMEM_TOTAL>>>(out);
}